// round 4
// baseline (speedup 1.0000x reference)
#include <cuda_runtime.h>
#include <cuda_fp16.h>

#define NN 100000
#define HH 4
#define CC 32
#define EE 1600000
#define IN_F 256
#define HC 128   // H*C
#define NEG_SLOPE 0.2f

// ---------------- device scratch (static, no allocation) ----------------
__device__ __half g_feat_h[(size_t)NN * HC];  // 25.6 MB [N,128] fp16 features
__device__ float g_el[NN * HH];               // [N,4]
__device__ float g_er[NN * HH];               // [N,4]
__device__ int g_deg[NN];
__device__ int g_scn[NN];
__device__ int g_rowstart[NN];
__device__ int g_cursor[NN];
__device__ int g_csrc[EE];                    // CSR: src node per dst-sorted edge
__device__ int g_chunk[128];
__device__ int g_chunkoff[128];

#define NCHUNK ((NN + 1023) / 1024)           // 98

// ---------------- CSR build ----------------
__global__ void zero_deg_kernel() {
    int i = blockIdx.x * blockDim.x + threadIdx.x;
    if (i < NN) g_deg[i] = 0;
}

__global__ void hist_kernel(const int* __restrict__ dst) {
    int e = blockIdx.x * blockDim.x + threadIdx.x;
    if (e < EE) atomicAdd(&g_deg[dst[e]], 1);
}

// 98 blocks x 1024: per-chunk exclusive scan + chunk totals
__global__ void scan_part_kernel() {
    __shared__ int wsum[32];
    int t = threadIdx.x;
    int i = blockIdx.x * 1024 + t;
    int v = (i < NN) ? g_deg[i] : 0;
    int lane = t & 31, w = t >> 5;
    int x = v;
#pragma unroll
    for (int o = 1; o < 32; o <<= 1) {
        int y = __shfl_up_sync(0xFFFFFFFFu, x, o);
        if (lane >= o) x += y;
    }
    if (lane == 31) wsum[w] = x;
    __syncthreads();
    if (w == 0) {
        int s = wsum[lane];
#pragma unroll
        for (int o = 1; o < 32; o <<= 1) {
            int y = __shfl_up_sync(0xFFFFFFFFu, s, o);
            if (lane >= o) s += y;
        }
        wsum[lane] = s;
    }
    __syncthreads();
    int excl = x - v + (w > 0 ? wsum[w - 1] : 0);
    if (i < NN) g_scn[i] = excl;
    if (t == 1023) g_chunk[blockIdx.x] = excl + v;
}

__global__ void scan_tot_kernel() {
    __shared__ int ws[4];
    int t = threadIdx.x;  // 128 threads
    int v = (t < NCHUNK) ? g_chunk[t] : 0;
    int lane = t & 31, w = t >> 5;
    int x = v;
#pragma unroll
    for (int o = 1; o < 32; o <<= 1) {
        int y = __shfl_up_sync(0xFFFFFFFFu, x, o);
        if (lane >= o) x += y;
    }
    if (lane == 31) ws[w] = x;
    __syncthreads();
    int add = 0;
    for (int j = 0; j < w; j++) add += ws[j];
    if (t < NCHUNK) g_chunkoff[t] = x - v + add;
}

__global__ void rowstart_kernel() {
    int i = blockIdx.x * blockDim.x + threadIdx.x;
    if (i < NN) {
        int rs = g_scn[i] + g_chunkoff[i >> 10];
        g_rowstart[i] = rs;
        g_cursor[i] = rs;
    }
}

__global__ void scatter_kernel(const int* __restrict__ src, const int* __restrict__ dst) {
    int e = blockIdx.x * blockDim.x + threadIdx.x;
    if (e < EE) {
        int d = dst[e];
        int p = atomicAdd(&g_cursor[d], 1);
        g_csrc[p] = src[e];
    }
}

// ---------------- GEMM: feat = X @ W via tf32 mma.sync, 2-stage pipeline ----------------
// M=100000 (BM=128/block), N=128 (full), K=256 in BK=16 tiles.
// 256 threads = 8 warps (4x2); warp tile 32x64; m16n8k8 fragments.
#define BM 128
#define BKP 16

__device__ __forceinline__ unsigned f2tf32(float f) {
    unsigned u;
    asm("cvt.rna.tf32.f32 %0, %1;" : "=r"(u) : "f"(f));
    return u;
}

__device__ __forceinline__ void mma_tf32(float* c, const unsigned* a, const unsigned* b) {
    asm volatile(
        "mma.sync.aligned.m16n8k8.row.col.f32.tf32.tf32.f32 "
        "{%0,%1,%2,%3}, {%4,%5,%6,%7}, {%8,%9}, {%0,%1,%2,%3};"
        : "+f"(c[0]), "+f"(c[1]), "+f"(c[2]), "+f"(c[3])
        : "r"(a[0]), "r"(a[1]), "r"(a[2]), "r"(a[3]), "r"(b[0]), "r"(b[1]));
}

__global__ __launch_bounds__(256) void gemm_kernel(const float* __restrict__ X,
                                                   const float* __restrict__ W,
                                                   const float* __restrict__ al,
                                                   const float* __restrict__ ar) {
    __shared__ unsigned As[2][BM][20];    // [buf][128][16+4pad] tf32 bits
    __shared__ unsigned Bs[2][BKP][136];  // [buf][16][128+8pad] tf32 bits

    int tid = threadIdx.x;
    int warp = tid >> 5;
    int lane = tid & 31;
    int warpm = warp >> 1;
    int warpn = warp & 1;
    int g = lane >> 2;
    int tig = lane & 3;
    int bm = blockIdx.x * BM;

    // load/store index decode (2 chunks per thread for each of A and B)
    int aid0 = tid * 2, aid1 = tid * 2 + 1;
    int ar0 = aid0 >> 2, ac0 = (aid0 & 3) * 4;
    int ar1 = aid1 >> 2, ac1 = (aid1 & 3) * 4;
    int bid0 = tid * 2, bid1 = tid * 2 + 1;
    int br0 = bid0 >> 5, bc0 = (bid0 & 31) * 4;
    int br1 = bid1 >> 5, bc1 = (bid1 & 31) * 4;

    float c[2][8][4];
#pragma unroll
    for (int mt = 0; mt < 2; mt++)
#pragma unroll
        for (int nt = 0; nt < 8; nt++)
#pragma unroll
            for (int r = 0; r < 4; r++) c[mt][nt][r] = 0.0f;

    float4 va0, va1, vb0, vb1;

    // ---- tile fetch to registers ----
    auto fetch = [&](int k0) {
        int gr0 = bm + ar0, gr1 = bm + ar1;
        va0 = (gr0 < NN) ? *(const float4*)(X + (size_t)gr0 * IN_F + k0 + ac0)
                         : make_float4(0.f, 0.f, 0.f, 0.f);
        va1 = (gr1 < NN) ? *(const float4*)(X + (size_t)gr1 * IN_F + k0 + ac1)
                         : make_float4(0.f, 0.f, 0.f, 0.f);
        vb0 = *(const float4*)(W + (size_t)(k0 + br0) * HC + bc0);
        vb1 = *(const float4*)(W + (size_t)(k0 + br1) * HC + bc1);
    };
    // ---- cvt + store regs to smem buffer ----
    auto deposit = [&](int buf) {
        *(uint4*)&As[buf][ar0][ac0] =
            make_uint4(f2tf32(va0.x), f2tf32(va0.y), f2tf32(va0.z), f2tf32(va0.w));
        *(uint4*)&As[buf][ar1][ac1] =
            make_uint4(f2tf32(va1.x), f2tf32(va1.y), f2tf32(va1.z), f2tf32(va1.w));
        *(uint4*)&Bs[buf][br0][bc0] =
            make_uint4(f2tf32(vb0.x), f2tf32(vb0.y), f2tf32(vb0.z), f2tf32(vb0.w));
        *(uint4*)&Bs[buf][br1][bc1] =
            make_uint4(f2tf32(vb1.x), f2tf32(vb1.y), f2tf32(vb1.z), f2tf32(vb1.w));
    };
    // ---- compute one BK=16 tile from smem buffer ----
    auto compute = [&](int buf) {
#pragma unroll
        for (int ks = 0; ks < 2; ks++) {
            int kk = ks * 8;
            unsigned a[2][4], b[8][2];
#pragma unroll
            for (int mt = 0; mt < 2; mt++) {
                int row = warpm * 32 + mt * 16;
                a[mt][0] = As[buf][row + g][kk + tig];
                a[mt][1] = As[buf][row + g + 8][kk + tig];
                a[mt][2] = As[buf][row + g][kk + tig + 4];
                a[mt][3] = As[buf][row + g + 8][kk + tig + 4];
            }
#pragma unroll
            for (int nt = 0; nt < 8; nt++) {
                int col = warpn * 64 + nt * 8 + g;
                b[nt][0] = Bs[buf][kk + tig][col];
                b[nt][1] = Bs[buf][kk + tig + 4][col];
            }
#pragma unroll
            for (int mt = 0; mt < 2; mt++)
#pragma unroll
                for (int nt = 0; nt < 8; nt++) mma_tf32(c[mt][nt], a[mt], b[nt]);
        }
    };

    // ---- pipelined mainloop ----
    fetch(0);
    deposit(0);
    __syncthreads();
    int buf = 0;
#pragma unroll
    for (int t = 1; t < IN_F / BKP; t++) {
        fetch(t * BKP);        // LDGs overlap with compute below
        compute(buf);
        deposit(buf ^ 1);      // waits on LDG results
        __syncthreads();
        buf ^= 1;
    }
    compute(buf);

    // ---- epilogue: fp16 feat store + fused el/er ----
    float alw[8][2], arw[8][2];
#pragma unroll
    for (int nt = 0; nt < 8; nt++) {
        int col = warpn * 64 + nt * 8 + tig * 2;
        alw[nt][0] = al[col];     alw[nt][1] = al[col + 1];
        arw[nt][0] = ar[col];     arw[nt][1] = ar[col + 1];
    }

#pragma unroll
    for (int mt = 0; mt < 2; mt++) {
#pragma unroll
        for (int rr = 0; rr < 2; rr++) {
            int row = bm + warpm * 32 + mt * 16 + rr * 8 + g;
            bool ok = (row < NN);
            float pl[2] = {0.f, 0.f}, pr[2] = {0.f, 0.f};
#pragma unroll
            for (int nt = 0; nt < 8; nt++) {
                float v0 = c[mt][nt][rr * 2];
                float v1 = c[mt][nt][rr * 2 + 1];
                int hh = nt >> 2;
                pl[hh] += v0 * alw[nt][0] + v1 * alw[nt][1];
                pr[hh] += v0 * arw[nt][0] + v1 * arw[nt][1];
                if (ok) {
                    __half2 hv = __floats2half2_rn(v0, v1);
                    int col = warpn * 64 + nt * 8 + tig * 2;
                    *(__half2*)(g_feat_h + (size_t)row * HC + col) = hv;
                }
            }
#pragma unroll
            for (int hh = 0; hh < 2; hh++) {
                pl[hh] += __shfl_xor_sync(0xFFFFFFFFu, pl[hh], 1);
                pl[hh] += __shfl_xor_sync(0xFFFFFFFFu, pl[hh], 2);
                pr[hh] += __shfl_xor_sync(0xFFFFFFFFu, pr[hh], 1);
                pr[hh] += __shfl_xor_sync(0xFFFFFFFFu, pr[hh], 2);
            }
            if (tig == 0 && ok) {
                int base = row * HH + warpn * 2;
                g_el[base + 0] = pl[0];
                g_el[base + 1] = pl[1];
                g_er[base + 0] = pr[0];
                g_er[base + 1] = pr[1];
            }
        }
    }
}

// ---------------- fused edge phase: warp per dst node ----------------
// Single pass over the node's CSR segment: accumulate s_h and ex-weighted
// feature sum in registers; normalize, head-average, +bias, relu, store out.
__global__ void edgeagg_kernel(const float* __restrict__ bias, float* __restrict__ out) {
    int w = (blockIdx.x * blockDim.x + threadIdx.x) >> 5;
    int lane = threadIdx.x & 31;
    if (w >= NN) return;

    float4 er4 = *(const float4*)(g_er + w * HH);
    int h = lane >> 3;                    // lane covers halves [4*lane, 4*lane+4): head h, c=(lane&7)*4
    float erh = (h & 2) ? ((h & 1) ? er4.w : er4.z) : ((h & 1) ? er4.y : er4.x);

    int start = g_rowstart[w];
    int deg = g_deg[w];
    float s = 0.f;
    float ax = 0.f, ay = 0.f, az = 0.f, aw = 0.f;

    for (int i = 0; i < deg; i++) {
        int si = g_csrc[start + i];                         // uniform -> broadcast
        float4 el4 = *(const float4*)(g_el + si * HH);      // uniform -> broadcast
        float elh = (h & 2) ? ((h & 1) ? el4.w : el4.z) : ((h & 1) ? el4.y : el4.x);
        float t = elh + erh;
        t = (t >= 0.f) ? t : NEG_SLOPE * t;
        float ex = __expf(t);
        s += ex;
        uint2 u = *(const uint2*)(g_feat_h + (size_t)si * HC + lane * 4);
        float2 f0 = __half22float2(*reinterpret_cast<__half2*>(&u.x));
        float2 f1 = __half22float2(*reinterpret_cast<__half2*>(&u.y));
        ax += ex * f0.x; ay += ex * f0.y; az += ex * f1.x; aw += ex * f1.y;
    }

    float inv = (s > 0.f) ? __fdividef(1.f, s) : 0.f;
    ax *= inv; ay *= inv; az *= inv; aw *= inv;

    // head-sum: lanes l, l^8, l^16, l^24 share c-range (lane&7)*4
    ax += __shfl_xor_sync(0xFFFFFFFFu, ax, 8);
    ax += __shfl_xor_sync(0xFFFFFFFFu, ax, 16);
    ay += __shfl_xor_sync(0xFFFFFFFFu, ay, 8);
    ay += __shfl_xor_sync(0xFFFFFFFFu, ay, 16);
    az += __shfl_xor_sync(0xFFFFFFFFu, az, 8);
    az += __shfl_xor_sync(0xFFFFFFFFu, az, 16);
    aw += __shfl_xor_sync(0xFFFFFFFFu, aw, 8);
    aw += __shfl_xor_sync(0xFFFFFFFFu, aw, 16);

    if (lane < 8) {
        int c = lane * 4;
        float4 o;
        float b0 = 0.25f * (bias[c + 0] + bias[CC + c + 0] + bias[2 * CC + c + 0] + bias[3 * CC + c + 0]);
        float b1 = 0.25f * (bias[c + 1] + bias[CC + c + 1] + bias[2 * CC + c + 1] + bias[3 * CC + c + 1]);
        float b2 = 0.25f * (bias[c + 2] + bias[CC + c + 2] + bias[2 * CC + c + 2] + bias[3 * CC + c + 2]);
        float b3 = 0.25f * (bias[c + 3] + bias[CC + c + 3] + bias[2 * CC + c + 3] + bias[3 * CC + c + 3]);
        o.x = fmaxf(0.25f * ax + b0, 0.f);
        o.y = fmaxf(0.25f * ay + b1, 0.f);
        o.z = fmaxf(0.25f * az + b2, 0.f);
        o.w = fmaxf(0.25f * aw + b3, 0.f);
        *(float4*)(out + (size_t)w * CC + c) = o;
    }
}

// ---------------- launch ----------------
extern "C" void kernel_launch(void* const* d_in, const int* in_sizes, int n_in,
                              void* d_out, int out_size) {
    const float* x      = (const float*)d_in[0];
    const int*   src    = (const int*)d_in[1];
    const int*   dst    = (const int*)d_in[2];
    const float* W      = (const float*)d_in[3];
    const float* attn_l = (const float*)d_in[4];
    const float* attn_r = (const float*)d_in[5];
    const float* bias   = (const float*)d_in[6];
    float* out = (float*)d_out;

    // CSR build
    zero_deg_kernel<<<(NN + 255) / 256, 256>>>();
    hist_kernel<<<(EE + 255) / 256, 256>>>(dst);
    scan_part_kernel<<<NCHUNK, 1024>>>();
    scan_tot_kernel<<<1, 128>>>();
    rowstart_kernel<<<(NN + 255) / 256, 256>>>();
    scatter_kernel<<<(EE + 255) / 256, 256>>>(src, dst);

    // GEMM + fused el/er + fp16 feat store
    gemm_kernel<<<(NN + BM - 1) / BM, 256>>>(x, W, attn_l, attn_r);

    // fused softmax + aggregate + bias/relu/output
    int threads = NN * 32;
    edgeagg_kernel<<<(threads + 255) / 256, 256>>>(bias, out);
}

// round 5
// speedup vs baseline: 1.3260x; 1.3260x over previous
#include <cuda_runtime.h>
#include <cuda_fp16.h>

#define NN 100000
#define HH 4
#define CC 32
#define EE 1600000
#define IN_F 256
#define HC 128   // H*C
#define NEG_SLOPE 0.2f

// ---------------- device scratch (static, no allocation) ----------------
__device__ __half g_feat_h[(size_t)NN * HC];  // 25.6 MB [N,128] fp16 features
__device__ float g_el[NN * HH];               // [N,4]
__device__ float g_er[NN * HH];               // [N,4]
__device__ float g_s[NN * HH];                // [N,4] softmax denominators
__device__ float g_ex[(size_t)EE * HH];       // 25.6 MB [E,4] exp(e)
__device__ float g_acc[NN * CC];              // 12.8 MB [N,32] head-summed aggregate

// ---------------- zero accumulators ----------------
__global__ void zero_kernel() {
    int i = blockIdx.x * blockDim.x + threadIdx.x;
    int total = NN * CC + NN * HH;
    if (i < NN * CC) g_acc[i] = 0.0f;
    else if (i < total) g_s[i - NN * CC] = 0.0f;
}

// ---------------- GEMM: feat = X @ W via fp16 mma.sync m16n8k16 ----------------
// M=100000 (BM=128/block), N=128 (full), K=256 in BK=16 tiles, double-buffered.
// 256 threads = 8 warps (4x2); warp tile 32x64; ldmatrix fragment loads.
#define BM 128
#define BKH 16

__device__ __forceinline__ void mma_f16(float* c, const unsigned* a, const unsigned* b) {
    asm volatile(
        "mma.sync.aligned.m16n8k16.row.col.f32.f16.f16.f32 "
        "{%0,%1,%2,%3}, {%4,%5,%6,%7}, {%8,%9}, {%0,%1,%2,%3};"
        : "+f"(c[0]), "+f"(c[1]), "+f"(c[2]), "+f"(c[3])
        : "r"(a[0]), "r"(a[1]), "r"(a[2]), "r"(a[3]), "r"(b[0]), "r"(b[1]));
}

__device__ __forceinline__ void ldsm_x4(unsigned* r, unsigned addr) {
    asm volatile("ldmatrix.sync.aligned.m8n8.x4.shared.b16 {%0,%1,%2,%3}, [%4];"
                 : "=r"(r[0]), "=r"(r[1]), "=r"(r[2]), "=r"(r[3]) : "r"(addr));
}
__device__ __forceinline__ void ldsm_x4_t(unsigned* r, unsigned addr) {
    asm volatile("ldmatrix.sync.aligned.m8n8.x4.trans.shared.b16 {%0,%1,%2,%3}, [%4];"
                 : "=r"(r[0]), "=r"(r[1]), "=r"(r[2]), "=r"(r[3]) : "r"(addr));
}

#define A_STRIDE 24   // halfs per A row (16 + 8 pad) -> 48B, LDSM conflict-free
#define B_STRIDE 136  // halfs per B row (128 + 8 pad) -> 272B, LDSM conflict-free

__global__ __launch_bounds__(256) void gemm_kernel(const float* __restrict__ X,
                                                   const float* __restrict__ W,
                                                   const float* __restrict__ al,
                                                   const float* __restrict__ ar) {
    __shared__ __half As[2][BM][A_STRIDE];
    __shared__ __half Bs[2][BKH][B_STRIDE];

    int tid = threadIdx.x;
    int warp = tid >> 5;
    int lane = tid & 31;
    int warpm = warp >> 1;   // 0..3 -> rows warpm*32
    int warpn = warp & 1;    // 0..1 -> cols warpn*64
    int g = lane >> 2;
    int tig = lane & 3;
    int bm = blockIdx.x * BM;

    // A-tile fetch decode: 512 float4 (128 rows x 4), 2 per thread
    int aid0 = tid * 2, aid1 = tid * 2 + 1;
    int ar0 = aid0 >> 2, ac0 = (aid0 & 3) * 4;
    int ar1 = aid1 >> 2, ac1 = (aid1 & 3) * 4;
    // B-tile fetch decode: 512 float4 (16 rows x 32), 2 per thread
    int br0 = aid0 >> 5, bc0 = (aid0 & 31) * 4;
    int br1 = aid1 >> 5, bc1 = (aid1 & 31) * 4;

    float c[2][8][4];
#pragma unroll
    for (int mt = 0; mt < 2; mt++)
#pragma unroll
        for (int nt = 0; nt < 8; nt++)
#pragma unroll
            for (int r = 0; r < 4; r++) c[mt][nt][r] = 0.0f;

    float4 va0, va1, vb0, vb1;

    auto fetch = [&](int k0) {
        int gr0 = bm + ar0, gr1 = bm + ar1;
        va0 = (gr0 < NN) ? *(const float4*)(X + (size_t)gr0 * IN_F + k0 + ac0)
                         : make_float4(0.f, 0.f, 0.f, 0.f);
        va1 = (gr1 < NN) ? *(const float4*)(X + (size_t)gr1 * IN_F + k0 + ac1)
                         : make_float4(0.f, 0.f, 0.f, 0.f);
        vb0 = *(const float4*)(W + (size_t)(k0 + br0) * HC + bc0);
        vb1 = *(const float4*)(W + (size_t)(k0 + br1) * HC + bc1);
    };
    auto deposit = [&](int buf) {
        __half2 a00 = __floats2half2_rn(va0.x, va0.y);
        __half2 a01 = __floats2half2_rn(va0.z, va0.w);
        __half2 a10 = __floats2half2_rn(va1.x, va1.y);
        __half2 a11 = __floats2half2_rn(va1.z, va1.w);
        *(__half2*)&As[buf][ar0][ac0] = a00;
        *(__half2*)&As[buf][ar0][ac0 + 2] = a01;
        *(__half2*)&As[buf][ar1][ac1] = a10;
        *(__half2*)&As[buf][ar1][ac1 + 2] = a11;
        __half2 b00 = __floats2half2_rn(vb0.x, vb0.y);
        __half2 b01 = __floats2half2_rn(vb0.z, vb0.w);
        __half2 b10 = __floats2half2_rn(vb1.x, vb1.y);
        __half2 b11 = __floats2half2_rn(vb1.z, vb1.w);
        *(__half2*)&Bs[buf][br0][bc0] = b00;
        *(__half2*)&Bs[buf][br0][bc0 + 2] = b01;
        *(__half2*)&Bs[buf][br1][bc1] = b10;
        *(__half2*)&Bs[buf][br1][bc1 + 2] = b11;
    };
    auto compute = [&](int buf) {
        // A fragments: 2 mt tiles of 16x16
        unsigned a[2][4];
#pragma unroll
        for (int mt = 0; mt < 2; mt++) {
            const __half* p = &As[buf][warpm * 32 + mt * 16 + (lane & 15)][(lane >> 4) * 8];
            ldsm_x4(a[mt], (unsigned)__cvta_generic_to_shared(p));
        }
        // B fragments: 4 x4.trans loads, each covering 2 nt tiles
        unsigned b[8][2];
#pragma unroll
        for (int pr = 0; pr < 4; pr++) {
            const __half* p = &Bs[buf][lane & 15][warpn * 64 + pr * 16 + (lane >> 4) * 8];
            unsigned t[4];
            ldsm_x4_t(t, (unsigned)__cvta_generic_to_shared(p));
            b[pr * 2][0] = t[0];     b[pr * 2][1] = t[1];
            b[pr * 2 + 1][0] = t[2]; b[pr * 2 + 1][1] = t[3];
        }
#pragma unroll
        for (int mt = 0; mt < 2; mt++)
#pragma unroll
            for (int nt = 0; nt < 8; nt++) mma_f16(c[mt][nt], a[mt], b[nt]);
    };

    // ---- pipelined mainloop: 16 BK=16 tiles ----
    fetch(0);
    deposit(0);
    __syncthreads();
    int buf = 0;
#pragma unroll
    for (int t = 1; t < IN_F / BKH; t++) {
        fetch(t * BKH);        // LDGs overlap with compute below
        compute(buf);
        deposit(buf ^ 1);
        __syncthreads();
        buf ^= 1;
    }
    compute(buf);

    // ---- epilogue: fp16 feat store + fused el/er ----
    float alw[8][2], arw[8][2];
#pragma unroll
    for (int nt = 0; nt < 8; nt++) {
        int col = warpn * 64 + nt * 8 + tig * 2;
        alw[nt][0] = al[col];     alw[nt][1] = al[col + 1];
        arw[nt][0] = ar[col];     arw[nt][1] = ar[col + 1];
    }

#pragma unroll
    for (int mt = 0; mt < 2; mt++) {
#pragma unroll
        for (int rr = 0; rr < 2; rr++) {
            int row = bm + warpm * 32 + mt * 16 + rr * 8 + g;
            bool ok = (row < NN);
            float pl[2] = {0.f, 0.f}, pr[2] = {0.f, 0.f};
#pragma unroll
            for (int nt = 0; nt < 8; nt++) {
                float v0 = c[mt][nt][rr * 2];
                float v1 = c[mt][nt][rr * 2 + 1];
                int hh = nt >> 2;
                pl[hh] += v0 * alw[nt][0] + v1 * alw[nt][1];
                pr[hh] += v0 * arw[nt][0] + v1 * arw[nt][1];
                if (ok) {
                    __half2 hv = __floats2half2_rn(v0, v1);
                    int col = warpn * 64 + nt * 8 + tig * 2;
                    *(__half2*)(g_feat_h + (size_t)row * HC + col) = hv;
                }
            }
#pragma unroll
            for (int hh = 0; hh < 2; hh++) {
                pl[hh] += __shfl_xor_sync(0xFFFFFFFFu, pl[hh], 1);
                pl[hh] += __shfl_xor_sync(0xFFFFFFFFu, pl[hh], 2);
                pr[hh] += __shfl_xor_sync(0xFFFFFFFFu, pr[hh], 1);
                pr[hh] += __shfl_xor_sync(0xFFFFFFFFu, pr[hh], 2);
            }
            if (tig == 0 && ok) {
                int base = row * HH + warpn * 2;
                g_el[base + 0] = pl[0];
                g_el[base + 1] = pl[1];
                g_er[base + 0] = pr[0];
                g_er[base + 1] = pr[1];
            }
        }
    }
}

// ---------------- edge pass 1: ex = exp(leaky(el[src]+er[dst])), s[dst] += ex ----------------
__device__ __forceinline__ float leaky_exp(float t) {
    float v = (t >= 0.f) ? t : NEG_SLOPE * t;
    return expf(v);
}

__global__ void edge1_kernel(const int* __restrict__ src, const int* __restrict__ dst) {
    int e = blockIdx.x * blockDim.x + threadIdx.x;
    if (e >= EE) return;
    int si = src[e];
    int di = dst[e];
    float4 l = *(const float4*)(g_el + (size_t)si * HH);
    float4 r = *(const float4*)(g_er + (size_t)di * HH);
    float4 ex;
    ex.x = leaky_exp(l.x + r.x);
    ex.y = leaky_exp(l.y + r.y);
    ex.z = leaky_exp(l.z + r.z);
    ex.w = leaky_exp(l.w + r.w);
    *(float4*)(g_ex + (size_t)e * HH) = ex;
    float* sp = g_s + (size_t)di * HH;
    asm volatile("red.global.add.v4.f32 [%0], {%1, %2, %3, %4};"
                 :: "l"(sp), "f"(ex.x), "f"(ex.y), "f"(ex.z), "f"(ex.w)
                 : "memory");
}

// ---------------- edge pass 2: acc[dst,c] += sum_h alpha[h] * feat_h[src,h,c] ----------------
// 4 lanes per edge, each lane handles 8 consecutive c (16B fp16 gathers per head).
__global__ void edge2_kernel(const int* __restrict__ src, const int* __restrict__ dst) {
    int idx = blockIdx.x * blockDim.x + threadIdx.x;
    int e = idx >> 2;
    int l4 = idx & 3;
    if (e >= EE) return;
    int si = src[e];
    int di = dst[e];
    float4 exv = *(const float4*)(g_ex + (size_t)e * HH);
    float4 sv = *(const float4*)(g_s + (size_t)di * HH);
    float ah[4];
    ah[0] = __fdividef(exv.x, sv.x);
    ah[1] = __fdividef(exv.y, sv.y);
    ah[2] = __fdividef(exv.z, sv.z);
    ah[3] = __fdividef(exv.w, sv.w);
    const __half* fp = g_feat_h + (size_t)si * HC + l4 * 8;
    float r[8];
#pragma unroll
    for (int j = 0; j < 8; j++) r[j] = 0.f;
#pragma unroll
    for (int h = 0; h < 4; h++) {
        uint4 u = *(const uint4*)(fp + h * CC);
        float2 f0 = __half22float2(*reinterpret_cast<__half2*>(&u.x));
        float2 f1 = __half22float2(*reinterpret_cast<__half2*>(&u.y));
        float2 f2 = __half22float2(*reinterpret_cast<__half2*>(&u.z));
        float2 f3 = __half22float2(*reinterpret_cast<__half2*>(&u.w));
        r[0] += ah[h] * f0.x;  r[1] += ah[h] * f0.y;
        r[2] += ah[h] * f1.x;  r[3] += ah[h] * f1.y;
        r[4] += ah[h] * f2.x;  r[5] += ah[h] * f2.y;
        r[6] += ah[h] * f3.x;  r[7] += ah[h] * f3.y;
    }
    float* ap = g_acc + (size_t)di * CC + l4 * 8;
    asm volatile("red.global.add.v4.f32 [%0], {%1, %2, %3, %4};"
                 :: "l"(ap), "f"(r[0]), "f"(r[1]), "f"(r[2]), "f"(r[3])
                 : "memory");
    asm volatile("red.global.add.v4.f32 [%0], {%1, %2, %3, %4};"
                 :: "l"(ap + 4), "f"(r[4]), "f"(r[5]), "f"(r[6]), "f"(r[7])
                 : "memory");
}

// ---------------- final: out = relu(acc/H + mean_h bias) ----------------
__global__ void final_kernel(const float* __restrict__ bias, float* __restrict__ out) {
    int i = blockIdx.x * blockDim.x + threadIdx.x;
    if (i >= NN * CC) return;
    int c = i & (CC - 1);
    float b = 0.25f * (bias[c] + bias[CC + c] + bias[2 * CC + c] + bias[3 * CC + c]);
    float v = g_acc[i] * 0.25f + b;
    out[i] = fmaxf(v, 0.0f);
}

// ---------------- launch ----------------
extern "C" void kernel_launch(void* const* d_in, const int* in_sizes, int n_in,
                              void* d_out, int out_size) {
    const float* x      = (const float*)d_in[0];
    const int*   src    = (const int*)d_in[1];
    const int*   dst    = (const int*)d_in[2];
    const float* W      = (const float*)d_in[3];
    const float* attn_l = (const float*)d_in[4];
    const float* attn_r = (const float*)d_in[5];
    const float* bias   = (const float*)d_in[6];
    float* out = (float*)d_out;

    {   // zero accumulators
        int total = NN * CC + NN * HH;
        zero_kernel<<<(total + 255) / 256, 256>>>();
    }
    {   // fp16 MMA GEMM + fused el/er + fp16 feat store
        gemm_kernel<<<(NN + BM - 1) / BM, 256>>>(x, W, attn_l, attn_r);
    }
    {   // edge pass 1
        edge1_kernel<<<(EE + 255) / 256, 256>>>(src, dst);
    }
    {   // edge pass 2
        long long threads = (long long)EE * 4;
        edge2_kernel<<<(int)((threads + 255) / 256), 256>>>(src, dst);
    }
    {   // final
        int threads = NN * CC;
        final_kernel<<<(threads + 255) / 256, 256>>>(bias, out);
    }
}